// round 16
// baseline (speedup 1.0000x reference)
#include <cuda_runtime.h>
#include <cuda_fp16.h>
#include <mma.h>
#include <cstdint>

using namespace nvcuda;

#define N_NODES 50000
#define IN_CH   128
#define EDGE_DIM 32
#define CAT_CH  (IN_CH + EDGE_DIM)   // 160
#define OUT_CH  128
#define BUCKET_CAP 128
#define KCHUNKS (CAT_CH / 16)        // 10
#define NTILES_N ((N_NODES + 15) / 16)

// Static device scratch (no allocations allowed; zero-initialized at load)
__device__ __align__(128) __half g_aggtile[(size_t)(NTILES_N + 8) * KCHUNKS * 256];
__device__ __align__(128) __half g_xh[(size_t)N_NODES * IN_CH];
__device__ __align__(128) __half g_wt[KCHUNKS * 8 * 256];
__device__ __align__(16)  uint2  g_edges8[(size_t)N_NODES * BUCKET_CAP];
__device__ int g_count[N_NODES];

// ---------------------------------------------------------------------------
// Kernel 1: x -> fp16
// ---------------------------------------------------------------------------
__global__ void prep_x_kernel(const float2* __restrict__ x2, int n2) {
    __half2* xdst = reinterpret_cast<__half2*>(g_xh);
    int i = blockIdx.x * blockDim.x + threadIdx.x;
    int stride = gridDim.x * blockDim.x;
    for (; i < n2; i += stride) {
        float2 v = __ldg(&x2[i]);
        xdst[i] = __float22half2_rn(v);
    }
}

// ---------------------------------------------------------------------------
// Kernel 2: W -> fp16 fragment-tiled + zero counts
// ---------------------------------------------------------------------------
__global__ void prep_w_kernel(const float* __restrict__ w, int N) {
    int i = blockIdx.x * blockDim.x + threadIdx.x;
    int stride = gridDim.x * blockDim.x;
    for (int k = i; k < CAT_CH * OUT_CH; k += stride) {
        int kr = k >> 7;
        int nc = k & 127;
        int dst = ((kr >> 4) * 8 + (nc >> 4)) * 256 + (kr & 15) * 16 + (nc & 15);
        g_wt[dst] = __float2half_rn(__ldg(&w[k]));
    }
    for (int k = i; k < N; k += stride) g_count[k] = 0;
}

// ---------------------------------------------------------------------------
// Kernel 3: bucket fill, 8B records {col<<16 | norm_fp16, e}
// ---------------------------------------------------------------------------
__device__ __forceinline__ void fill_one(int r, int c, float nm, int e) {
    int pos = atomicAdd(&g_count[r], 1);
    if (pos < BUCKET_CAP) {
        unsigned hb = __half_as_ushort(__float2half_rn(nm));
        g_edges8[(size_t)r * BUCKET_CAP + pos] =
            make_uint2(((unsigned)c << 16) | hb, (unsigned)e);
    }
}

__global__ void fill_kernel(const int4*   __restrict__ row4,
                            const int4*   __restrict__ col4,
                            const float4* __restrict__ norm4,
                            int E4,
                            const int* __restrict__ row,
                            const int* __restrict__ col,
                            const float* __restrict__ norm,
                            int E) {
    int i = blockIdx.x * blockDim.x + threadIdx.x;
    if (i < E4) {
        int4   r  = __ldg(&row4[i]);
        int4   c  = __ldg(&col4[i]);
        float4 nm = __ldg(&norm4[i]);
        int e = i * 4;
        fill_one(r.x, c.x, nm.x, e + 0);
        fill_one(r.y, c.y, nm.y, e + 1);
        fill_one(r.z, c.z, nm.z, e + 2);
        fill_one(r.w, c.w, nm.w, e + 3);
    }
    if (i == 0) {
        for (int t = E4 * 4; t < E; t++) fill_one(row[t], col[t], norm[t], t);
    }
}

// ---------------------------------------------------------------------------
// Kernel 4 (PROFILED): aggregation, 2 edges per LDG.
// One warp per node. half = lane>>4 selects edge within a pair; sub = lane&15.
// Per pair: lane loads uint4 (8 fp16 x-channels) + float2 (2 ea channels).
// Records: 4 x uint4 broadcast loads per 8-edge group (2 records per load).
// Cross-half shfl reduction at the end; lanes 0-15 store.
// Slots >= cnt are never written -> zero records (w=0), safe col=0/e=0.
// ---------------------------------------------------------------------------
__global__ void aggregate_kernel(const float* __restrict__ ea, int N) {
    int n    = (blockIdx.x * blockDim.x + threadIdx.x) >> 5;
    int lane = threadIdx.x & 31;
    if (n >= N) return;

    int half = lane >> 4;
    int sub  = lane & 15;

    int cnt = __ldg(&g_count[n]);
    if (cnt > BUCKET_CAP) cnt = BUCKET_CAP;

    const uint2* bucket = g_edges8 + (size_t)n * BUCKET_CAP;
    const uint4* xh4 = reinterpret_cast<const uint4*>(g_xh);   // 16 uint4 per row
    const float2* ea2 = reinterpret_cast<const float2*>(ea);   // 16 float2 per row

    float accx[8];
    #pragma unroll
    for (int k = 0; k < 8; k++) accx[k] = 0.f;
    float acce0 = 0.f, acce1 = 0.f;

    for (int j = 0; j < cnt; j += 8) {
        // 8 records via 4 vector broadcast loads
        uint4 rec[4];
        #pragma unroll
        for (int q = 0; q < 4; q++)
            rec[q] = __ldg(reinterpret_cast<const uint4*>(bucket + j + q * 2));

        #pragma unroll
        for (int p = 0; p < 4; p++) {
            unsigned rx = half ? rec[p].z : rec[p].x;
            unsigned re = half ? rec[p].w : rec[p].y;
            bool valid = (j + 2 * p + half) < cnt;
            float w = valid
                ? __half2float(__ushort_as_half((unsigned short)(rx & 0xFFFFu)))
                : 0.f;
            unsigned c = rx >> 16;

            uint4  xv = __ldg(&xh4[(size_t)c * 16 + sub]);
            float2 ev = __ldg(&ea2[(size_t)re * 16 + sub]);

            float2 f;
            f = __half22float2(*reinterpret_cast<__half2*>(&xv.x));
            accx[0] += w * f.x; accx[1] += w * f.y;
            f = __half22float2(*reinterpret_cast<__half2*>(&xv.y));
            accx[2] += w * f.x; accx[3] += w * f.y;
            f = __half22float2(*reinterpret_cast<__half2*>(&xv.z));
            accx[4] += w * f.x; accx[5] += w * f.y;
            f = __half22float2(*reinterpret_cast<__half2*>(&xv.w));
            accx[6] += w * f.x; accx[7] += w * f.y;
            acce0 += w * ev.x;
            acce1 += w * ev.y;
        }
    }

    // cross-half reduction: lane s (half 0) accumulates lane s+16's partials
    #pragma unroll
    for (int k = 0; k < 8; k++)
        accx[k] += __shfl_down_sync(0xffffffffu, accx[k], 16);
    acce0 += __shfl_down_sync(0xffffffffu, acce0, 16);
    acce1 += __shfl_down_sync(0xffffffffu, acce1, 16);

    if (half == 0) {
        int t  = n >> 4;
        int rr = n & 15;
        __half* base = g_aggtile + (size_t)t * (KCHUNKS * 256);

        // x channels [sub*8, sub*8+8): chunk = sub/2, col = (sub&1)*8
        __half2 h0 = __floats2half2_rn(accx[0], accx[1]);
        __half2 h1 = __floats2half2_rn(accx[2], accx[3]);
        __half2 h2 = __floats2half2_rn(accx[4], accx[5]);
        __half2 h3 = __floats2half2_rn(accx[6], accx[7]);
        uint4 st;
        st.x = *reinterpret_cast<uint32_t*>(&h0);
        st.y = *reinterpret_cast<uint32_t*>(&h1);
        st.z = *reinterpret_cast<uint32_t*>(&h2);
        st.w = *reinterpret_cast<uint32_t*>(&h3);
        *reinterpret_cast<uint4*>(base + (sub >> 1) * 256 + rr * 16 + (sub & 1) * 8) = st;

        // edge channels [sub*2, sub*2+2): chunk 8 + (sub*2)/16, col = (sub*2)&15
        int c0 = sub * 2;
        __half2 he = __floats2half2_rn(acce0, acce1);
        *reinterpret_cast<__half2*>(base + (8 + (c0 >> 4)) * 256 + rr * 16 + (c0 & 15)) =
            he;
    }
}

// ---------------------------------------------------------------------------
// Kernel 5: persistent GEMM, register-resident W fragments (unchanged).
// ---------------------------------------------------------------------------
#define C_LD 132
#define SC_WORDS (32 * C_LD)

__global__ void __launch_bounds__(256, 2)
gemm_wmma_kernel(const float* __restrict__ b,
                 float* __restrict__ out, int N, int ngroups) {
    __shared__ float sC[SC_WORDS];

    int tid = threadIdx.x;
    int wid = tid >> 5;
    int lane = tid & 31;
    int mi = wid & 1;
    int ng = wid >> 1;

    wmma::fragment<wmma::matrix_b, 16, 16, 16, __half, wmma::row_major> wf[KCHUNKS][2];
    #pragma unroll
    for (int k = 0; k < KCHUNKS; k++) {
        #pragma unroll
        for (int f = 0; f < 2; f++) {
            wmma::load_matrix_sync(wf[k][f],
                g_wt + ((size_t)k * 8 + (ng * 2 + f)) * 256, 16);
        }
    }

    float4 bias = __ldg(reinterpret_cast<const float4*>(b) + lane);

    for (int g = blockIdx.x; g < ngroups; g += gridDim.x) {
        int tile = g * 2 + mi;
        const __half* A = g_aggtile + (size_t)tile * (KCHUNKS * 256);

        wmma::fragment<wmma::accumulator, 16, 16, 16, float> acc[2];
        wmma::fill_fragment(acc[0], 0.0f);
        wmma::fill_fragment(acc[1], 0.0f);

        #pragma unroll
        for (int k = 0; k < KCHUNKS; k++) {
            wmma::fragment<wmma::matrix_a, 16, 16, 16, __half, wmma::row_major> a;
            wmma::load_matrix_sync(a, A + k * 256, 16);
            wmma::mma_sync(acc[0], a, wf[k][0], acc[0]);
            wmma::mma_sync(acc[1], a, wf[k][1], acc[1]);
        }

        float* cd = sC + mi * 16 * C_LD + ng * 32;
        wmma::store_matrix_sync(cd,      acc[0], C_LD, wmma::mem_row_major);
        wmma::store_matrix_sync(cd + 16, acc[1], C_LD, wmma::mem_row_major);
        __syncthreads();

        int row0 = g * 32;
        #pragma unroll
        for (int p = 0; p < 4; p++) {
            int r = p * 8 + wid;
            int grow = row0 + r;
            if (grow < N) {
                float4 v = *reinterpret_cast<const float4*>(sC + r * C_LD + lane * 4);
                v.x += bias.x; v.y += bias.y; v.z += bias.z; v.w += bias.w;
                reinterpret_cast<float4*>(out + (size_t)grow * OUT_CH)[lane] = v;
            }
        }
        __syncthreads();
    }
}

// ---------------------------------------------------------------------------
// Launch: 5 kernels; aggregate is the 4th launch (profiled slot).
// ---------------------------------------------------------------------------
extern "C" void kernel_launch(void* const* d_in, const int* in_sizes, int n_in,
                              void* d_out, int out_size) {
    const float* x         = (const float*)d_in[0];
    const int*   row       = (const int*)  d_in[1];
    const int*   col       = (const int*)  d_in[2];
    const float* norm      = (const float*)d_in[3];
    const float* edge_attr = (const float*)d_in[4];
    const float* W         = (const float*)d_in[5];
    const float* b         = (const float*)d_in[6];
    float* out = (float*)d_out;

    int N = in_sizes[0] / IN_CH;
    int E = in_sizes[1];
    int E4 = E / 4;
    int ngroups = (N + 31) / 32;

    prep_x_kernel<<<2048, 512>>>(reinterpret_cast<const float2*>(x), (N * IN_CH) / 2);
    prep_w_kernel<<<256, 256>>>(W, N);
    fill_kernel<<<(E4 + 255) / 256, 256>>>(
        reinterpret_cast<const int4*>(row),
        reinterpret_cast<const int4*>(col),
        reinterpret_cast<const float4*>(norm), E4,
        row, col, norm, E);
    aggregate_kernel<<<(N + 7) / 8, 256>>>(edge_attr, N);
    gemm_wmma_kernel<<<592, 256>>>(b, out, N, ngroups);
}

// round 17
// speedup vs baseline: 1.0585x; 1.0585x over previous
#include <cuda_runtime.h>
#include <cuda_fp16.h>
#include <mma.h>
#include <cstdint>

using namespace nvcuda;

#define N_NODES 50000
#define IN_CH   128
#define EDGE_DIM 32
#define CAT_CH  (IN_CH + EDGE_DIM)   // 160
#define OUT_CH  128
#define BUCKET_CAP 128
#define KCHUNKS (CAT_CH / 16)        // 10
#define NTILES_N ((N_NODES + 15) / 16)

// Static device scratch (no allocations allowed; zero-initialized at load)
__device__ __align__(128) __half g_aggtile[(size_t)(NTILES_N + 8) * KCHUNKS * 256];
__device__ __align__(128) __half g_xh[(size_t)N_NODES * IN_CH];
__device__ __align__(128) __half g_wt[KCHUNKS * 8 * 256];
__device__ __align__(16)  uint2  g_edges8[(size_t)N_NODES * BUCKET_CAP];
__device__ int g_count[N_NODES];

// ---------------------------------------------------------------------------
// Kernel 1: fused prep = x->fp16 + W->fp16 fragment-tiled + zero counts
// ---------------------------------------------------------------------------
__global__ void prep_kernel(const float2* __restrict__ x2, int n2,
                            const float* __restrict__ w, int N) {
    int i = blockIdx.x * blockDim.x + threadIdx.x;
    int stride = gridDim.x * blockDim.x;

    __half2* xdst = reinterpret_cast<__half2*>(g_xh);
    for (int k = i; k < n2; k += stride) {
        float2 v = __ldg(&x2[k]);
        xdst[k] = __float22half2_rn(v);
    }
    for (int k = i; k < CAT_CH * OUT_CH; k += stride) {
        int kr = k >> 7;
        int nc = k & 127;
        int dst = ((kr >> 4) * 8 + (nc >> 4)) * 256 + (kr & 15) * 16 + (nc & 15);
        g_wt[dst] = __float2half_rn(__ldg(&w[k]));
    }
    for (int k = i; k < N; k += stride) g_count[k] = 0;
}

// ---------------------------------------------------------------------------
// Kernel 2: bucket fill, 8B records {col<<16 | norm_fp16, e}  (R15 config)
// ---------------------------------------------------------------------------
__device__ __forceinline__ void fill_one(int r, int c, float nm, int e) {
    int pos = atomicAdd(&g_count[r], 1);
    if (pos < BUCKET_CAP) {
        unsigned hb = __half_as_ushort(__float2half_rn(nm));
        g_edges8[(size_t)r * BUCKET_CAP + pos] =
            make_uint2(((unsigned)c << 16) | hb, (unsigned)e);
    }
}

__global__ void fill_kernel(const int4*   __restrict__ row4,
                            const int4*   __restrict__ col4,
                            const float4* __restrict__ norm4,
                            int E4,
                            const int* __restrict__ row,
                            const int* __restrict__ col,
                            const float* __restrict__ norm,
                            int E) {
    int i = blockIdx.x * blockDim.x + threadIdx.x;
    if (i < E4) {
        int4   r  = __ldg(&row4[i]);
        int4   c  = __ldg(&col4[i]);
        float4 nm = __ldg(&norm4[i]);
        int e = i * 4;
        fill_one(r.x, c.x, nm.x, e + 0);
        fill_one(r.y, c.y, nm.y, e + 1);
        fill_one(r.z, c.z, nm.z, e + 2);
        fill_one(r.w, c.w, nm.w, e + 3);
    }
    if (i == 0) {
        for (int t = E4 * 4; t < E; t++) fill_one(row[t], col[t], norm[t], t);
    }
}

// ---------------------------------------------------------------------------
// Kernel 3: aggregation (R15 winner, restored verbatim).
// One warp per node; 8B records; x fp16 gather (8B/lane); ea fp32 gather;
// fp32 accumulate; fragment-tiled store. At the L2 traffic floor (~86us).
// ---------------------------------------------------------------------------
__device__ __forceinline__ void acc_half4(float4& acc, uint2 u, float nm) {
    float2 f01 = __half22float2(*reinterpret_cast<__half2*>(&u.x));
    float2 f23 = __half22float2(*reinterpret_cast<__half2*>(&u.y));
    acc.x += nm * f01.x; acc.y += nm * f01.y;
    acc.z += nm * f23.x; acc.w += nm * f23.y;
}

__global__ void aggregate_kernel(const float* __restrict__ ea, int N) {
    int n    = (blockIdx.x * blockDim.x + threadIdx.x) >> 5;
    int lane = threadIdx.x & 31;
    if (n >= N) return;

    int cnt = __ldg(&g_count[n]);
    if (cnt > BUCKET_CAP) cnt = BUCKET_CAP;

    const uint2* bucket = g_edges8 + (size_t)n * BUCKET_CAP;
    const uint2* xh = reinterpret_cast<const uint2*>(g_xh);

    float4 acc = make_float4(0.f, 0.f, 0.f, 0.f);
    float  acce = 0.f;

    int full = cnt & ~7;
    int j = 0;
    for (; j < full; j += 8) {
        uint2 r[8];
        #pragma unroll
        for (int q = 0; q < 8; q++) r[q] = __ldg(&bucket[j + q]);
        uint2 u[8];
        #pragma unroll
        for (int q = 0; q < 8; q++)
            u[q] = __ldg(&xh[(r[q].x >> 16) * (IN_CH / 4) + (unsigned)lane]);
        float g[8];
        #pragma unroll
        for (int q = 0; q < 8; q++)
            g[q] = __ldg(&ea[(size_t)r[q].y * EDGE_DIM + lane]);
        #pragma unroll
        for (int q = 0; q < 8; q++) {
            float w = __half2float(__ushort_as_half((unsigned short)(r[q].x & 0xFFFF)));
            acc_half4(acc, u[q], w);
            acce += w * g[q];
        }
    }
    if (j < cnt) {
        uint2 r[8];
        float w[8];
        #pragma unroll
        for (int q = 0; q < 8; q++) {
            int idx  = j + q;
            int slot = (idx < cnt) ? idx : 0;
            r[q] = __ldg(&bucket[slot]);
            w[q] = (idx < cnt)
                 ? __half2float(__ushort_as_half((unsigned short)(r[q].x & 0xFFFF)))
                 : 0.f;
        }
        uint2 u[8];
        #pragma unroll
        for (int q = 0; q < 8; q++)
            u[q] = __ldg(&xh[(r[q].x >> 16) * (IN_CH / 4) + (unsigned)lane]);
        float g[8];
        #pragma unroll
        for (int q = 0; q < 8; q++)
            g[q] = __ldg(&ea[(size_t)r[q].y * EDGE_DIM + lane]);
        #pragma unroll
        for (int q = 0; q < 8; q++) {
            acc_half4(acc, u[q], w[q]);
            acce += w[q] * g[q];
        }
    }

    int t  = n >> 4;
    int rr = n & 15;
    __half* base = g_aggtile + (size_t)t * (KCHUNKS * 256);

    __half2 h01 = __floats2half2_rn(acc.x, acc.y);
    __half2 h23 = __floats2half2_rn(acc.z, acc.w);
    uint2 st;
    st.x = *reinterpret_cast<uint32_t*>(&h01);
    st.y = *reinterpret_cast<uint32_t*>(&h23);
    *reinterpret_cast<uint2*>(base + (lane >> 2) * 256 + rr * 16 + (lane & 3) * 4) = st;
    base[(8 + (lane >> 4)) * 256 + rr * 16 + (lane & 15)] = __float2half_rn(acce);
}

// ---------------------------------------------------------------------------
// Kernel 4: persistent GEMM, register-resident W fragments.
// Grid halved to 296 (2 blocks/SM): W fragment traffic 48.5 -> 24 MB.
// ---------------------------------------------------------------------------
#define C_LD 132
#define SC_WORDS (32 * C_LD)

__global__ void __launch_bounds__(256, 2)
gemm_wmma_kernel(const float* __restrict__ b,
                 float* __restrict__ out, int N, int ngroups) {
    __shared__ float sC[SC_WORDS];

    int tid = threadIdx.x;
    int wid = tid >> 5;
    int lane = tid & 31;
    int mi = wid & 1;
    int ng = wid >> 1;

    wmma::fragment<wmma::matrix_b, 16, 16, 16, __half, wmma::row_major> wf[KCHUNKS][2];
    #pragma unroll
    for (int k = 0; k < KCHUNKS; k++) {
        #pragma unroll
        for (int f = 0; f < 2; f++) {
            wmma::load_matrix_sync(wf[k][f],
                g_wt + ((size_t)k * 8 + (ng * 2 + f)) * 256, 16);
        }
    }

    float4 bias = __ldg(reinterpret_cast<const float4*>(b) + lane);

    for (int g = blockIdx.x; g < ngroups; g += gridDim.x) {
        int tile = g * 2 + mi;
        const __half* A = g_aggtile + (size_t)tile * (KCHUNKS * 256);

        wmma::fragment<wmma::accumulator, 16, 16, 16, float> acc[2];
        wmma::fill_fragment(acc[0], 0.0f);
        wmma::fill_fragment(acc[1], 0.0f);

        #pragma unroll
        for (int k = 0; k < KCHUNKS; k++) {
            wmma::fragment<wmma::matrix_a, 16, 16, 16, __half, wmma::row_major> a;
            wmma::load_matrix_sync(a, A + k * 256, 16);
            wmma::mma_sync(acc[0], a, wf[k][0], acc[0]);
            wmma::mma_sync(acc[1], a, wf[k][1], acc[1]);
        }

        float* cd = sC + mi * 16 * C_LD + ng * 32;
        wmma::store_matrix_sync(cd,      acc[0], C_LD, wmma::mem_row_major);
        wmma::store_matrix_sync(cd + 16, acc[1], C_LD, wmma::mem_row_major);
        __syncthreads();

        int row0 = g * 32;
        #pragma unroll
        for (int p = 0; p < 4; p++) {
            int r = p * 8 + wid;
            int grow = row0 + r;
            if (grow < N) {
                float4 v = *reinterpret_cast<const float4*>(sC + r * C_LD + lane * 4);
                v.x += bias.x; v.y += bias.y; v.z += bias.z; v.w += bias.w;
                reinterpret_cast<float4*>(out + (size_t)grow * OUT_CH)[lane] = v;
            }
        }
        __syncthreads();
    }
}

// ---------------------------------------------------------------------------
// Launch: 4 kernels; gemm is the 4th launch (profiled slot).
// ---------------------------------------------------------------------------
extern "C" void kernel_launch(void* const* d_in, const int* in_sizes, int n_in,
                              void* d_out, int out_size) {
    const float* x         = (const float*)d_in[0];
    const int*   row       = (const int*)  d_in[1];
    const int*   col       = (const int*)  d_in[2];
    const float* norm      = (const float*)d_in[3];
    const float* edge_attr = (const float*)d_in[4];
    const float* W         = (const float*)d_in[5];
    const float* b         = (const float*)d_in[6];
    float* out = (float*)d_out;

    int N = in_sizes[0] / IN_CH;
    int E = in_sizes[1];
    int E4 = E / 4;
    int ngroups = (N + 31) / 32;

    // 1) fused prep
    prep_kernel<<<2048, 512>>>(reinterpret_cast<const float2*>(x),
                               (N * IN_CH) / 2, W, N);

    // 2) bucket fill
    fill_kernel<<<(E4 + 255) / 256, 256>>>(
        reinterpret_cast<const int4*>(row),
        reinterpret_cast<const int4*>(col),
        reinterpret_cast<const float4*>(norm), E4,
        row, col, norm, E);

    // 3) aggregation -> fragment-tiled A (R15 winner)
    aggregate_kernel<<<(N + 7) / 8, 256>>>(edge_attr, N);

    // 4) persistent GEMM + bias (profiled)
    gemm_wmma_kernel<<<296, 256>>>(b, out, N, ngroups);
}